// round 15
// baseline (speedup 1.0000x reference)
#include <cuda_runtime.h>
#include <cuda_fp16.h>
#include <cstdint>

#define DINLINE __device__ __forceinline__

static constexpr int M_TOT = 8192;
static constexpr int N_TOT = 4096;
static constexpr int K_TOT = 4096;

static constexpr int BM = 128;
static constexpr int BN = 64;
static constexpr int BK = 64;                 // fp16 elems per k-chunk (128B rows)
static constexpr int NK = K_TOT / BK;         // 64 mainloop iterations

static constexpr int A_BYTES = BM * BK * 2;            // 16384
static constexpr int B_BYTES = BN * BK * 2;            // 8192
static constexpr int STAGE_BYTES = A_BYTES + B_BYTES;  // 24576
static constexpr int NSTAGE = 3;
static constexpr int SMEM_TOTAL = NSTAGE * STAGE_BYTES; // 73728 per CTA (3 CTAs/SM)

// ------------------- scratch (device globals; no allocation) -------------------
__device__ __align__(128) __half g_xh[(size_t)M_TOT * K_TOT];   // 64 MB
__device__ __align__(128) __half g_wh[(size_t)N_TOT * K_TOT];   // 32 MB

// ------------------- PTX helpers (sm_80-base features only) -------------------
DINLINE uint32_t smem_u32(const void* p) {
    uint32_t a;
    asm("{ .reg .u64 t; cvta.to.shared.u64 t, %1; cvt.u32.u64 %0, t; }" : "=r"(a) : "l"(p));
    return a;
}
DINLINE void cp16(uint32_t dst, const void* src) {
    asm volatile("cp.async.cg.shared.global [%0], [%1], 16;" :: "r"(dst), "l"(src) : "memory");
}
DINLINE void cp_commit() { asm volatile("cp.async.commit_group;" ::: "memory"); }
template <int N> DINLINE void cp_wait() {
    asm volatile("cp.async.wait_group %0;" :: "n"(N) : "memory");
}
DINLINE void ldsm_x4(uint32_t* r, uint32_t addr) {
    asm volatile("ldmatrix.sync.aligned.m8n8.x4.shared.b16 {%0,%1,%2,%3}, [%4];"
                 : "=r"(r[0]), "=r"(r[1]), "=r"(r[2]), "=r"(r[3]) : "r"(addr));
}
DINLINE void mma_f16(float* d, const uint32_t* a, uint32_t b0, uint32_t b1) {
    asm volatile(
        "mma.sync.aligned.m16n8k16.row.col.f32.f16.f16.f32 "
        "{%0,%1,%2,%3}, {%4,%5,%6,%7}, {%8,%9}, {%0,%1,%2,%3};"
        : "+f"(d[0]), "+f"(d[1]), "+f"(d[2]), "+f"(d[3])
        : "r"(a[0]), "r"(a[1]), "r"(a[2]), "r"(a[3]), "r"(b0), "r"(b1));
}

// ------------------- merged prep: fp32 -> fp16 for both tensors -------------------
DINLINE uint32_t pack_h2(__half a, __half b) {
    return (uint32_t)__half_as_ushort(a) | ((uint32_t)__half_as_ushort(b) << 16);
}
static constexpr size_t X_ELEMS = (size_t)M_TOT * K_TOT;   // 33.55M
__global__ void __launch_bounds__(256) prep2_kernel(const float* __restrict__ x,
                                                    const float* __restrict__ w,
                                                    __half* __restrict__ xh,
                                                    __half* __restrict__ wh) {
    size_t i8 = ((size_t)blockIdx.x * 256u + threadIdx.x) * 8u;
    const float* src;
    __half* dst;
    if (i8 < X_ELEMS) { src = x + i8; dst = xh + i8; }
    else              { src = w + (i8 - X_ELEMS); dst = wh + (i8 - X_ELEMS); }
    const float4* p = reinterpret_cast<const float4*>(src);
    float4 v0 = p[0], v1 = p[1];
    uint32_t ph[4];
    ph[0] = pack_h2(__float2half_rn(v0.x), __float2half_rn(v0.y));
    ph[1] = pack_h2(__float2half_rn(v0.z), __float2half_rn(v0.w));
    ph[2] = pack_h2(__float2half_rn(v1.x), __float2half_rn(v1.y));
    ph[3] = pack_h2(__float2half_rn(v1.z), __float2half_rn(v1.w));
    *reinterpret_cast<uint4*>(dst) = make_uint4(ph[0], ph[1], ph[2], ph[3]);
}

// ------------------- GEMM: 128x64 CTA, 4 warps 64x32, 3-stage ring, 3 CTAs/SM -------------------
// 128B smem rows, swizzle: chunk' = chunk ^ (row & 7)
// 3-stage ring: ONE barrier per kt; refill of stage (kt+2)%3 issues right after the
// barrier (its last readers finished at kt-1, proven by this barrier), overlapping
// the whole kt body of frag loads + MMAs.
__global__ void __launch_bounds__(128, 3) gemm_fp16_kernel(float* __restrict__ out) {
    extern __shared__ char smem[];
    const uint32_t sb = smem_u32(smem);
    const int tid  = threadIdx.x;
    const int wid  = tid >> 5;
    const int lane = tid & 31;
    const int wm = wid >> 1;        // 0..1  (M dir, 64 rows each)
    const int wn = wid & 1;         // 0..1  (N dir, 32 cols each)
    const int mbase = blockIdx.y * BM;
    const int nbase = blockIdx.x * BN;

    // cp.async geometry: 8 lanes x 16B cover one 128B row; 128 thr -> 16 rows/round
    const int lr = tid >> 3;        // 0..15 (row group)
    const int lc = tid & 7;         // chunk index (0..7)

    auto load_stage = [&](int kt, int stg) {
        const uint32_t s0 = sb + stg * STAGE_BYTES;
        const size_t gk = (size_t)kt * BK + (size_t)lc * 8;
#pragma unroll
        for (int i = 0; i < 8; i++) {   // A: 128 rows
            const int row = lr + i * 16;
            const uint32_t d = (uint32_t)row * 128u + (uint32_t)((lc ^ (row & 7)) << 4);
            cp16(s0 + d, g_xh + (size_t)(mbase + row) * K_TOT + gk);
        }
#pragma unroll
        for (int i = 0; i < 4; i++) {   // B: 64 rows
            const int row = lr + i * 16;
            const uint32_t d = (uint32_t)row * 128u + (uint32_t)((lc ^ (row & 7)) << 4);
            cp16(s0 + A_BYTES + d, g_wh + (size_t)(nbase + row) * K_TOT + gk);
        }
    };

    float acc[4][4][4];
#pragma unroll
    for (int a = 0; a < 4; a++)
#pragma unroll
        for (int b = 0; b < 4; b++)
#pragma unroll
            for (int c = 0; c < 4; c++) acc[a][b][c] = 0.0f;

    load_stage(0, 0); cp_commit();
    load_stage(1, 1); cp_commit();

    // ldmatrix lane-constant base offsets: P = row*128 + ((row&7)<<4); addr = base + (P ^ (chunk<<4))
    const uint32_t a_lrow = (uint32_t)(lane & 15);
    const uint32_t a_lchnk = (uint32_t)(lane >> 4);          // 0/1 -> k half
    const uint32_t b_lrow = (uint32_t)((lane & 7) + ((lane >> 4) << 3));
    const uint32_t b_lchnk = (uint32_t)((lane >> 3) & 1);

    uint32_t aP[4], bP[2];
#pragma unroll
    for (int mf = 0; mf < 4; mf++) {
        const uint32_t row = (uint32_t)(wm * 64 + mf * 16) + a_lrow;
        aP[mf] = row * 128u + ((row & 7u) << 4);
    }
#pragma unroll
    for (int p = 0; p < 2; p++) {
        const uint32_t row = (uint32_t)(wn * 32 + p * 16) + b_lrow;
        bP[p] = (uint32_t)A_BYTES + row * 128u + ((row & 7u) << 4);
    }

    uint32_t ah[2][4][4], bh[2][8];

    auto load_frags = [&](uint32_t base, int s, int buf) {
        const uint32_t ax = ((2u * (uint32_t)s + a_lchnk) << 4);
        const uint32_t bx = ((2u * (uint32_t)s + b_lchnk) << 4);
#pragma unroll
        for (int mf = 0; mf < 4; mf++) ldsm_x4(ah[buf][mf], base + (aP[mf] ^ ax));
#pragma unroll
        for (int p = 0; p < 2; p++)    ldsm_x4(&bh[buf][p * 4], base + (bP[p] ^ bx));
    };

    auto mma_slice = [&](int buf) {
#pragma unroll
        for (int mf = 0; mf < 4; mf++) {
#pragma unroll
            for (int nf = 0; nf < 4; nf++) {
                const int p = nf >> 1, q = nf & 1;
                mma_f16(acc[mf][nf], ah[buf][mf],
                        bh[buf][p * 4 + 2 * q], bh[buf][p * 4 + 2 * q + 1]);
            }
        }
    };

    int stg = 0;            // stage to read this kt
    int rfl = 2;            // stage to refill this kt (= last read at kt-1)
#pragma unroll 1
    for (int kt = 0; kt < NK; kt++) {
        cp_wait<1>();               // my own group for stage stg is done
        __syncthreads();            // => everyone's group for stage stg is done;
                                    //    and everyone finished reading stage rfl (at kt-1)

        const uint32_t base = sb + stg * STAGE_BYTES;
        load_frags(base, 0, 0);                      // slice-0 frags first (latency critical)
        if (kt + 2 < NK) load_stage(kt + 2, rfl);    // refill early: overlaps whole kt body
        cp_commit();                                 // exactly one group per kt (may be empty)

#pragma unroll
        for (int s = 0; s < 4; s++) {                // four k16 slices of BK=64
            const int cur = s & 1, nxt = cur ^ 1;
            if (s < 3) load_frags(base, s + 1, nxt); // prefetch next slice's frags
            mma_slice(cur);
        }

        stg = (stg == 2) ? 0 : stg + 1;
        rfl = (rfl == 2) ? 0 : rfl + 1;
    }

    // ------------------- epilogue -------------------
    const int gid = lane >> 2;          // 0..7 (row in frag)
    const int tg  = lane & 3;           // 0..3 (col pair)
    float* ob = out + (size_t)mbase * N_TOT + nbase;
#pragma unroll
    for (int mf = 0; mf < 4; mf++) {
#pragma unroll
        for (int nf = 0; nf < 4; nf++) {
            const int r = wm * 64 + mf * 16 + gid;
            const int c = wn * 32 + nf * 8 + tg * 2;
            *reinterpret_cast<float2*>(ob + (size_t)r * N_TOT + c) =
                make_float2(acc[mf][nf][0], acc[mf][nf][1]);
            *reinterpret_cast<float2*>(ob + (size_t)(r + 8) * N_TOT + c) =
                make_float2(acc[mf][nf][2], acc[mf][nf][3]);
        }
    }
}

// ------------------- launch -------------------
extern "C" void kernel_launch(void* const* d_in, const int* in_sizes, int n_in,
                              void* d_out, int out_size) {
    const float* x = (const float*)d_in[0];
    const float* w = (const float*)d_in[1];
    // robustness: identify tensors by element count (x: 8192*4096=33.5M, w: 4096*4096=16.8M)
    if (n_in >= 2 && in_sizes[0] == N_TOT * K_TOT) {
        x = (const float*)d_in[1];
        w = (const float*)d_in[0];
    }
    float* out = (float*)d_out;

    __half *xh, *wh;
    cudaGetSymbolAddress((void**)&xh, g_xh);
    cudaGetSymbolAddress((void**)&wh, g_wh);

    const size_t total8 = ((size_t)M_TOT * K_TOT + (size_t)N_TOT * K_TOT) / 8;  // 6.29M
    prep2_kernel<<<(int)(total8 / 256), 256>>>(x, w, xh, wh);

    cudaFuncSetAttribute(gemm_fp16_kernel,
                         cudaFuncAttributeMaxDynamicSharedMemorySize, SMEM_TOTAL);
    gemm_fp16_kernel<<<dim3(N_TOT / BN, M_TOT / BM), 128, SMEM_TOTAL>>>(out);
}

// round 16
// speedup vs baseline: 1.3753x; 1.3753x over previous
#include <cuda_runtime.h>
#include <cuda_fp16.h>
#include <cstdint>

#define DINLINE __device__ __forceinline__

static constexpr int M_TOT = 8192;
static constexpr int N_TOT = 4096;
static constexpr int K_TOT = 4096;

static constexpr int BM = 128;
static constexpr int BN = 64;
static constexpr int BK = 64;                 // fp16 elems per k-chunk (128B rows)
static constexpr int NK = K_TOT / BK;         // 64 mainloop iterations

static constexpr int A_BYTES = BM * BK * 2;            // 16384
static constexpr int B_BYTES = BN * BK * 2;            // 8192
static constexpr int STAGE_BYTES = A_BYTES + B_BYTES;  // 24576
static constexpr int NSTAGE = 2;
static constexpr int SMEM_TOTAL = NSTAGE * STAGE_BYTES; // 49152 per CTA (4 CTAs/SM)

// ------------------- scratch (device globals; no allocation) -------------------
__device__ __align__(128) __half g_xh[(size_t)M_TOT * K_TOT];   // 64 MB
__device__ __align__(128) __half g_wh[(size_t)N_TOT * K_TOT];   // 32 MB

// ------------------- PTX helpers (sm_80-base features only) -------------------
DINLINE uint32_t smem_u32(const void* p) {
    uint32_t a;
    asm("{ .reg .u64 t; cvta.to.shared.u64 t, %1; cvt.u32.u64 %0, t; }" : "=r"(a) : "l"(p));
    return a;
}
DINLINE void cp16(uint32_t dst, const void* src) {
    asm volatile("cp.async.cg.shared.global [%0], [%1], 16;" :: "r"(dst), "l"(src) : "memory");
}
DINLINE void cp_commit() { asm volatile("cp.async.commit_group;" ::: "memory"); }
template <int N> DINLINE void cp_wait() {
    asm volatile("cp.async.wait_group %0;" :: "n"(N) : "memory");
}
DINLINE void ldsm_x4(uint32_t* r, uint32_t addr) {
    asm volatile("ldmatrix.sync.aligned.m8n8.x4.shared.b16 {%0,%1,%2,%3}, [%4];"
                 : "=r"(r[0]), "=r"(r[1]), "=r"(r[2]), "=r"(r[3]) : "r"(addr));
}
DINLINE void mma_f16(float* d, const uint32_t* a, uint32_t b0, uint32_t b1) {
    asm volatile(
        "mma.sync.aligned.m16n8k16.row.col.f32.f16.f16.f32 "
        "{%0,%1,%2,%3}, {%4,%5,%6,%7}, {%8,%9}, {%0,%1,%2,%3};"
        : "+f"(d[0]), "+f"(d[1]), "+f"(d[2]), "+f"(d[3])
        : "r"(a[0]), "r"(a[1]), "r"(a[2]), "r"(a[3]), "r"(b0), "r"(b1));
}

// ------------------- merged prep: fp32 -> fp16 for both tensors -------------------
DINLINE uint32_t pack_h2(__half a, __half b) {
    return (uint32_t)__half_as_ushort(a) | ((uint32_t)__half_as_ushort(b) << 16);
}
static constexpr size_t X_ELEMS = (size_t)M_TOT * K_TOT;   // 33.55M
__global__ void __launch_bounds__(256) prep2_kernel(const float* __restrict__ x,
                                                    const float* __restrict__ w,
                                                    __half* __restrict__ xh,
                                                    __half* __restrict__ wh) {
    size_t i8 = ((size_t)blockIdx.x * 256u + threadIdx.x) * 8u;
    const float* src;
    __half* dst;
    if (i8 < X_ELEMS) { src = x + i8; dst = xh + i8; }
    else              { src = w + (i8 - X_ELEMS); dst = wh + (i8 - X_ELEMS); }
    const float4* p = reinterpret_cast<const float4*>(src);
    float4 v0 = p[0], v1 = p[1];
    uint32_t ph[4];
    ph[0] = pack_h2(__float2half_rn(v0.x), __float2half_rn(v0.y));
    ph[1] = pack_h2(__float2half_rn(v0.z), __float2half_rn(v0.w));
    ph[2] = pack_h2(__float2half_rn(v1.x), __float2half_rn(v1.y));
    ph[3] = pack_h2(__float2half_rn(v1.z), __float2half_rn(v1.w));
    *reinterpret_cast<uint4*>(dst) = make_uint4(ph[0], ph[1], ph[2], ph[3]);
}

// ------------------- GEMM: 128x64 CTA, 4 warps 64x32, 4 CTAs/SM, frag pipeline -------------------
// 128B smem rows, swizzle: chunk' = chunk ^ (row & 7)
// Schedule: f0,f1,m0,f2,m1,f3, sync, refill+commit, m2,m3 — 32 MMAs cover the refill burst.
__global__ void __launch_bounds__(128, 4) gemm_fp16_kernel(float* __restrict__ out) {
    extern __shared__ char smem[];
    const uint32_t sb = smem_u32(smem);
    const int tid  = threadIdx.x;
    const int wid  = tid >> 5;
    const int lane = tid & 31;
    const int wm = wid >> 1;        // 0..1  (M dir, 64 rows each)
    const int wn = wid & 1;         // 0..1  (N dir, 32 cols each)
    const int mbase = blockIdx.y * BM;
    const int nbase = blockIdx.x * BN;

    // cp.async geometry: 8 lanes x 16B cover one 128B row; 128 thr -> 16 rows/round
    const int lr = tid >> 3;        // 0..15 (row group)
    const int lc = tid & 7;         // chunk index (0..7)

    auto load_stage = [&](int kt, int stg) {
        const uint32_t s0 = sb + stg * STAGE_BYTES;
        const size_t gk = (size_t)kt * BK + (size_t)lc * 8;
#pragma unroll
        for (int i = 0; i < 8; i++) {   // A: 128 rows
            const int row = lr + i * 16;
            const uint32_t d = (uint32_t)row * 128u + (uint32_t)((lc ^ (row & 7)) << 4);
            cp16(s0 + d, g_xh + (size_t)(mbase + row) * K_TOT + gk);
        }
#pragma unroll
        for (int i = 0; i < 4; i++) {   // B: 64 rows
            const int row = lr + i * 16;
            const uint32_t d = (uint32_t)row * 128u + (uint32_t)((lc ^ (row & 7)) << 4);
            cp16(s0 + A_BYTES + d, g_wh + (size_t)(nbase + row) * K_TOT + gk);
        }
    };

    float acc[4][4][4];
#pragma unroll
    for (int a = 0; a < 4; a++)
#pragma unroll
        for (int b = 0; b < 4; b++)
#pragma unroll
            for (int c = 0; c < 4; c++) acc[a][b][c] = 0.0f;

    load_stage(0, 0); cp_commit();
    load_stage(1, 1); cp_commit();

    // ldmatrix lane-constant base offsets: P = row*128 + ((row&7)<<4); addr = base + (P ^ (chunk<<4))
    const uint32_t a_lrow = (uint32_t)(lane & 15);
    const uint32_t a_lchnk = (uint32_t)(lane >> 4);          // 0/1 -> k half
    const uint32_t b_lrow = (uint32_t)((lane & 7) + ((lane >> 4) << 3));
    const uint32_t b_lchnk = (uint32_t)((lane >> 3) & 1);

    uint32_t aP[4], bP[2];
#pragma unroll
    for (int mf = 0; mf < 4; mf++) {
        const uint32_t row = (uint32_t)(wm * 64 + mf * 16) + a_lrow;
        aP[mf] = row * 128u + ((row & 7u) << 4);
    }
#pragma unroll
    for (int p = 0; p < 2; p++) {
        const uint32_t row = (uint32_t)(wn * 32 + p * 16) + b_lrow;
        bP[p] = (uint32_t)A_BYTES + row * 128u + ((row & 7u) << 4);
    }

    uint32_t ah[2][4][4], bh[2][8];

    auto load_frags = [&](uint32_t base, int s, int buf) {
        const uint32_t ax = ((2u * (uint32_t)s + a_lchnk) << 4);
        const uint32_t bx = ((2u * (uint32_t)s + b_lchnk) << 4);
#pragma unroll
        for (int mf = 0; mf < 4; mf++) ldsm_x4(ah[buf][mf], base + (aP[mf] ^ ax));
#pragma unroll
        for (int p = 0; p < 2; p++)    ldsm_x4(&bh[buf][p * 4], base + (bP[p] ^ bx));
    };

    auto mma_slice = [&](int buf) {
#pragma unroll
        for (int mf = 0; mf < 4; mf++) {
#pragma unroll
            for (int nf = 0; nf < 4; nf++) {
                const int p = nf >> 1, q = nf & 1;
                mma_f16(acc[mf][nf], ah[buf][mf],
                        bh[buf][p * 4 + 2 * q], bh[buf][p * 4 + 2 * q + 1]);
            }
        }
    };

    int stg = 0;
#pragma unroll 1
    for (int kt = 0; kt < NK; kt++) {
        cp_wait<1>();
        __syncthreads();

        const uint32_t base = sb + stg * STAGE_BYTES;
        load_frags(base, 0, 0);     // f0
        load_frags(base, 1, 1);     // f1
        mma_slice(0);               // m0   (reads buf0; f2 below overwrites buf0 after)
        load_frags(base, 2, 0);     // f2
        mma_slice(1);               // m1   (reads buf1; f3 below overwrites buf1 after)
        load_frags(base, 3, 1);     // f3   -- ALL smem reads of this stage now issued

        __syncthreads();            // stage fully consumed block-wide
        if (kt + 2 < NK) load_stage(kt + 2, stg);   // refill; 32 MMAs below cover the burst
        cp_commit();

        mma_slice(0);               // m2
        mma_slice(1);               // m3

        stg ^= 1;
    }

    // ------------------- epilogue -------------------
    const int gid = lane >> 2;          // 0..7 (row in frag)
    const int tg  = lane & 3;           // 0..3 (col pair)
    float* ob = out + (size_t)mbase * N_TOT + nbase;
#pragma unroll
    for (int mf = 0; mf < 4; mf++) {
#pragma unroll
        for (int nf = 0; nf < 4; nf++) {
            const int r = wm * 64 + mf * 16 + gid;
            const int c = wn * 32 + nf * 8 + tg * 2;
            *reinterpret_cast<float2*>(ob + (size_t)r * N_TOT + c) =
                make_float2(acc[mf][nf][0], acc[mf][nf][1]);
            *reinterpret_cast<float2*>(ob + (size_t)(r + 8) * N_TOT + c) =
                make_float2(acc[mf][nf][2], acc[mf][nf][3]);
        }
    }
}

// ------------------- launch -------------------
extern "C" void kernel_launch(void* const* d_in, const int* in_sizes, int n_in,
                              void* d_out, int out_size) {
    const float* x = (const float*)d_in[0];
    const float* w = (const float*)d_in[1];
    // robustness: identify tensors by element count (x: 8192*4096=33.5M, w: 4096*4096=16.8M)
    if (n_in >= 2 && in_sizes[0] == N_TOT * K_TOT) {
        x = (const float*)d_in[1];
        w = (const float*)d_in[0];
    }
    float* out = (float*)d_out;

    __half *xh, *wh;
    cudaGetSymbolAddress((void**)&xh, g_xh);
    cudaGetSymbolAddress((void**)&wh, g_wh);

    const size_t total8 = ((size_t)M_TOT * K_TOT + (size_t)N_TOT * K_TOT) / 8;  // 6.29M
    prep2_kernel<<<(int)(total8 / 256), 256>>>(x, w, xh, wh);

    cudaFuncSetAttribute(gemm_fp16_kernel,
                         cudaFuncAttributeMaxDynamicSharedMemorySize, SMEM_TOTAL);
    gemm_fp16_kernel<<<dim3(N_TOT / BN, M_TOT / BM), 128, SMEM_TOTAL>>>(out);
}

// round 17
// speedup vs baseline: 1.6048x; 1.1668x over previous
#include <cuda_runtime.h>
#include <cuda_fp16.h>
#include <cstdint>

#define DINLINE __device__ __forceinline__

static constexpr int M_TOT = 8192;
static constexpr int N_TOT = 4096;
static constexpr int K_TOT = 4096;

static constexpr int BM = 128;
static constexpr int BN = 64;
static constexpr int BK = 64;                 // fp16 elems per k-chunk (128B rows)
static constexpr int NK = K_TOT / BK;         // 64 mainloop iterations

static constexpr int A_BYTES = BM * BK * 2;            // 16384
static constexpr int B_BYTES = BN * BK * 2;            // 8192
static constexpr int STAGE_BYTES = A_BYTES + B_BYTES;  // 24576
static constexpr int NSTAGE = 2;
static constexpr int SMEM_TOTAL = NSTAGE * STAGE_BYTES; // 49152 per CTA (4 CTAs/SM)

// ------------------- scratch (device globals; no allocation) -------------------
__device__ __align__(128) __half g_xh[(size_t)M_TOT * K_TOT];   // 64 MB
__device__ __align__(128) __half g_wh[(size_t)N_TOT * K_TOT];   // 32 MB

// ------------------- PTX helpers (sm_80-base features only) -------------------
DINLINE uint32_t smem_u32(const void* p) {
    uint32_t a;
    asm("{ .reg .u64 t; cvta.to.shared.u64 t, %1; cvt.u32.u64 %0, t; }" : "=r"(a) : "l"(p));
    return a;
}
DINLINE void cp16(uint32_t dst, const void* src) {
    asm volatile("cp.async.cg.shared.global [%0], [%1], 16;" :: "r"(dst), "l"(src) : "memory");
}
DINLINE void cp_commit() { asm volatile("cp.async.commit_group;" ::: "memory"); }
template <int N> DINLINE void cp_wait() {
    asm volatile("cp.async.wait_group %0;" :: "n"(N) : "memory");
}
DINLINE void ldsm_x4(uint32_t* r, uint32_t addr) {
    asm volatile("ldmatrix.sync.aligned.m8n8.x4.shared.b16 {%0,%1,%2,%3}, [%4];"
                 : "=r"(r[0]), "=r"(r[1]), "=r"(r[2]), "=r"(r[3]) : "r"(addr));
}
DINLINE void mma_f16(float* d, const uint32_t* a, uint32_t b0, uint32_t b1) {
    asm volatile(
        "mma.sync.aligned.m16n8k16.row.col.f32.f16.f16.f32 "
        "{%0,%1,%2,%3}, {%4,%5,%6,%7}, {%8,%9}, {%0,%1,%2,%3};"
        : "+f"(d[0]), "+f"(d[1]), "+f"(d[2]), "+f"(d[3])
        : "r"(a[0]), "r"(a[1]), "r"(a[2]), "r"(a[3]), "r"(b0), "r"(b1));
}

// ------------------- merged prep: fp32 -> fp16 for both tensors -------------------
DINLINE uint32_t pack_h2(__half a, __half b) {
    return (uint32_t)__half_as_ushort(a) | ((uint32_t)__half_as_ushort(b) << 16);
}
static constexpr size_t X_ELEMS = (size_t)M_TOT * K_TOT;   // 33.55M
__global__ void __launch_bounds__(256) prep2_kernel(const float* __restrict__ x,
                                                    const float* __restrict__ w,
                                                    __half* __restrict__ xh,
                                                    __half* __restrict__ wh) {
    size_t i8 = ((size_t)blockIdx.x * 256u + threadIdx.x) * 8u;
    const float* src;
    __half* dst;
    if (i8 < X_ELEMS) { src = x + i8; dst = xh + i8; }
    else              { src = w + (i8 - X_ELEMS); dst = wh + (i8 - X_ELEMS); }
    const float4* p = reinterpret_cast<const float4*>(src);
    float4 v0 = p[0], v1 = p[1];
    uint32_t ph[4];
    ph[0] = pack_h2(__float2half_rn(v0.x), __float2half_rn(v0.y));
    ph[1] = pack_h2(__float2half_rn(v0.z), __float2half_rn(v0.w));
    ph[2] = pack_h2(__float2half_rn(v1.x), __float2half_rn(v1.y));
    ph[3] = pack_h2(__float2half_rn(v1.z), __float2half_rn(v1.w));
    *reinterpret_cast<uint4*>(dst) = make_uint4(ph[0], ph[1], ph[2], ph[3]);
}

// ------------------- GEMM: 128x64 CTA, 4 warps 64x32, 4 CTAs/SM, frag pipeline -------------------
// 128B smem rows, swizzle: chunk' = chunk ^ (row & 7)
__global__ void __launch_bounds__(128, 4) gemm_fp16_kernel(float* __restrict__ out) {
    extern __shared__ char smem[];
    const uint32_t sb = smem_u32(smem);
    const int tid  = threadIdx.x;
    const int wid  = tid >> 5;
    const int lane = tid & 31;
    const int wm = wid >> 1;        // 0..1  (M dir, 64 rows each)
    const int wn = wid & 1;         // 0..1  (N dir, 32 cols each)
    const int mbase = blockIdx.y * BM;
    const int nbase = blockIdx.x * BN;

    // cp.async geometry: 8 lanes x 16B cover one 128B row; 128 thr -> 16 rows/round
    const int lr = tid >> 3;        // 0..15 (row group)
    const int lc = tid & 7;         // chunk index (0..7)

    auto load_stage = [&](int kt, int stg) {
        const uint32_t s0 = sb + stg * STAGE_BYTES;
        const size_t gk = (size_t)kt * BK + (size_t)lc * 8;
#pragma unroll
        for (int i = 0; i < 8; i++) {   // A: 128 rows
            const int row = lr + i * 16;
            const uint32_t d = (uint32_t)row * 128u + (uint32_t)((lc ^ (row & 7)) << 4);
            cp16(s0 + d, g_xh + (size_t)(mbase + row) * K_TOT + gk);
        }
#pragma unroll
        for (int i = 0; i < 4; i++) {   // B: 64 rows
            const int row = lr + i * 16;
            const uint32_t d = (uint32_t)row * 128u + (uint32_t)((lc ^ (row & 7)) << 4);
            cp16(s0 + A_BYTES + d, g_wh + (size_t)(nbase + row) * K_TOT + gk);
        }
    };

    float acc[4][4][4];
#pragma unroll
    for (int a = 0; a < 4; a++)
#pragma unroll
        for (int b = 0; b < 4; b++)
#pragma unroll
            for (int c = 0; c < 4; c++) acc[a][b][c] = 0.0f;

    load_stage(0, 0); cp_commit();
    load_stage(1, 1); cp_commit();

    // ldmatrix lane-constant base offsets: P = row*128 + ((row&7)<<4); addr = base + (P ^ (chunk<<4))
    const uint32_t a_lrow = (uint32_t)(lane & 15);
    const uint32_t a_lchnk = (uint32_t)(lane >> 4);          // 0/1 -> k half
    const uint32_t b_lrow = (uint32_t)((lane & 7) + ((lane >> 4) << 3));
    const uint32_t b_lchnk = (uint32_t)((lane >> 3) & 1);

    uint32_t aP[4], bP[2];
#pragma unroll
    for (int mf = 0; mf < 4; mf++) {
        const uint32_t row = (uint32_t)(wm * 64 + mf * 16) + a_lrow;
        aP[mf] = row * 128u + ((row & 7u) << 4);
    }
#pragma unroll
    for (int p = 0; p < 2; p++) {
        const uint32_t row = (uint32_t)(wn * 32 + p * 16) + b_lrow;
        bP[p] = (uint32_t)A_BYTES + row * 128u + ((row & 7u) << 4);
    }

    uint32_t ah[2][4][4], bh[2][8];

    auto load_frags = [&](uint32_t base, int s, int buf) {
        const uint32_t ax = ((2u * (uint32_t)s + a_lchnk) << 4);
        const uint32_t bx = ((2u * (uint32_t)s + b_lchnk) << 4);
#pragma unroll
        for (int mf = 0; mf < 4; mf++) ldsm_x4(ah[buf][mf], base + (aP[mf] ^ ax));
#pragma unroll
        for (int p = 0; p < 2; p++)    ldsm_x4(&bh[buf][p * 4], base + (bP[p] ^ bx));
    };

    auto mma_slice = [&](int buf) {
#pragma unroll
        for (int mf = 0; mf < 4; mf++) {
#pragma unroll
            for (int nf = 0; nf < 4; nf++) {
                const int p = nf >> 1, q = nf & 1;
                mma_f16(acc[mf][nf], ah[buf][mf],
                        bh[buf][p * 4 + 2 * q], bh[buf][p * 4 + 2 * q + 1]);
            }
        }
    };

    int stg = 0;
#pragma unroll 1
    for (int kt = 0; kt < NK; kt++) {
        cp_wait<1>();
        __syncthreads();

        const uint32_t base = sb + stg * STAGE_BYTES;
        load_frags(base, 0, 0);                      // slice-0 frags: latency overlaps MMA of s=0..
#pragma unroll
        for (int s = 0; s < 4; s++) {                // four k16 slices of BK=64
            const int cur = s & 1, nxt = cur ^ 1;
            if (s < 3) load_frags(base, s + 1, nxt); // prefetch next slice's frags
            mma_slice(cur);
        }

        __syncthreads();                             // all reads of this stage done
        if (kt + 2 < NK) load_stage(kt + 2, stg);    // refill same buffer
        cp_commit();

        stg ^= 1;
    }

    // ------------------- epilogue -------------------
    const int gid = lane >> 2;          // 0..7 (row in frag)
    const int tg  = lane & 3;           // 0..3 (col pair)
    float* ob = out + (size_t)mbase * N_TOT + nbase;
#pragma unroll
    for (int mf = 0; mf < 4; mf++) {
#pragma unroll
        for (int nf = 0; nf < 4; nf++) {
            const int r = wm * 64 + mf * 16 + gid;
            const int c = wn * 32 + nf * 8 + tg * 2;
            *reinterpret_cast<float2*>(ob + (size_t)r * N_TOT + c) =
                make_float2(acc[mf][nf][0], acc[mf][nf][1]);
            *reinterpret_cast<float2*>(ob + (size_t)(r + 8) * N_TOT + c) =
                make_float2(acc[mf][nf][2], acc[mf][nf][3]);
        }
    }
}

// ------------------- launch -------------------
extern "C" void kernel_launch(void* const* d_in, const int* in_sizes, int n_in,
                              void* d_out, int out_size) {
    const float* x = (const float*)d_in[0];
    const float* w = (const float*)d_in[1];
    // robustness: identify tensors by element count (x: 8192*4096=33.5M, w: 4096*4096=16.8M)
    if (n_in >= 2 && in_sizes[0] == N_TOT * K_TOT) {
        x = (const float*)d_in[1];
        w = (const float*)d_in[0];
    }
    float* out = (float*)d_out;

    __half *xh, *wh;
    cudaGetSymbolAddress((void**)&xh, g_xh);
    cudaGetSymbolAddress((void**)&wh, g_wh);

    const size_t total8 = ((size_t)M_TOT * K_TOT + (size_t)N_TOT * K_TOT) / 8;  // 6.29M
    prep2_kernel<<<(int)(total8 / 256), 256>>>(x, w, xh, wh);

    cudaFuncSetAttribute(gemm_fp16_kernel,
                         cudaFuncAttributeMaxDynamicSharedMemorySize, SMEM_TOTAL);
    gemm_fp16_kernel<<<dim3(N_TOT / BN, M_TOT / BM), 128, SMEM_TOTAL>>>(out);
}